// round 1
// baseline (speedup 1.0000x reference)
#include <cuda_runtime.h>
#include <math.h>

#define N 4096
#define DIN 64
#define DOUT 64
#define NEG_HUGE (-3.402823466e38f)

// Scratch (device-global, no allocation at runtime)
__device__ float g_P[(size_t)N * N];   // 64 MB: P = I + t0*S + t1*S^2
__device__ float g_dinv[N];            // 1/sqrt(rowsum(A))
__device__ float g_c[N];               // 1/rowsum(A)
__device__ float g_e[N];               // 1/sqrt(rowsum(P))
__device__ float g_t[2];               // sigmoid(theta)

// ---------------------------------------------------------------------------
// Kernel 1: row sums of A -> dinv, c ; also sigmoid(theta)
// ---------------------------------------------------------------------------
__global__ __launch_bounds__(256) void k_rowsum_A(const float* __restrict__ A,
                                                  const float* __restrict__ theta) {
    int row = blockIdx.x;
    const float4* a4 = (const float4*)(A + (size_t)row * N);
    float s = 0.f;
    for (int i = threadIdx.x; i < N / 4; i += 256) {
        float4 v = a4[i];
        s += v.x + v.y + v.z + v.w;
    }
    __shared__ float red[256];
    red[threadIdx.x] = s;
    __syncthreads();
    for (int o = 128; o > 0; o >>= 1) {
        if (threadIdx.x < o) red[threadIdx.x] += red[threadIdx.x + o];
        __syncthreads();
    }
    if (threadIdx.x == 0) {
        float d = red[0];
        g_dinv[row] = rsqrtf(d);
        g_c[row] = 1.0f / d;
        if (row == 0) {
            g_t[0] = 1.0f / (1.0f + expf(-theta[0]));
            g_t[1] = 1.0f / (1.0f + expf(-theta[1]));
        }
    }
}

// ---------------------------------------------------------------------------
// Kernel 2: M = A * diag(c) * A  (128x128 tile, 8x8 microtile, fp32)
// Fused epilogue: P = I + dinv_i*dinv_j*(t0*A + t1*M)
// ---------------------------------------------------------------------------
#define BT 128
#define KT 16
#define SPAD 4

__global__ __launch_bounds__(256) void k_gemm_poly(const float* __restrict__ A) {
    __shared__ float As[KT][BT + SPAD];   // As[kk][i] = A[i0+i][k0+kk] * c[k0+kk]
    __shared__ float Bs[KT][BT + SPAD];   // Bs[kk][j] = A[k0+kk][j0+j]
    int tid = threadIdx.x;
    int i0 = blockIdx.y * BT, j0 = blockIdx.x * BT;
    int ty = tid >> 4, tx = tid & 15;

    float acc[8][8];
#pragma unroll
    for (int r = 0; r < 8; r++)
#pragma unroll
        for (int cl = 0; cl < 8; cl++) acc[r][cl] = 0.f;

    for (int k0 = 0; k0 < N; k0 += KT) {
        // left tile: 128 rows x 16 k-cols, scaled by c[k]
        int id = tid;
#pragma unroll
        for (int s = 0; s < 2; s++, id += 256) {
            int r = id >> 2, cg = id & 3;
            float4 v = *(const float4*)(A + (size_t)(i0 + r) * N + k0 + cg * 4);
            float4 cc = *(const float4*)(g_c + k0 + cg * 4);
            As[cg * 4 + 0][r] = v.x * cc.x;
            As[cg * 4 + 1][r] = v.y * cc.y;
            As[cg * 4 + 2][r] = v.z * cc.z;
            As[cg * 4 + 3][r] = v.w * cc.w;
        }
        // right tile: 16 k-rows x 128 cols
        id = tid;
#pragma unroll
        for (int s = 0; s < 2; s++, id += 256) {
            int r = id >> 5, cg = id & 31;
            *(float4*)&Bs[r][cg * 4] =
                *(const float4*)(A + (size_t)(k0 + r) * N + j0 + cg * 4);
        }
        __syncthreads();

#pragma unroll
        for (int kk = 0; kk < KT; kk++) {
            float a[8], b[8];
            *(float4*)&a[0] = *(float4*)&As[kk][ty * 8];
            *(float4*)&a[4] = *(float4*)&As[kk][ty * 8 + 4];
            *(float4*)&b[0] = *(float4*)&Bs[kk][tx * 8];
            *(float4*)&b[4] = *(float4*)&Bs[kk][tx * 8 + 4];
#pragma unroll
            for (int r = 0; r < 8; r++)
#pragma unroll
                for (int cl = 0; cl < 8; cl++) acc[r][cl] += a[r] * b[cl];
        }
        __syncthreads();
    }

    float t0 = g_t[0], t1 = g_t[1];
    float di[8], dj[8];
#pragma unroll
    for (int r = 0; r < 8; r++) di[r] = g_dinv[i0 + ty * 8 + r];
#pragma unroll
    for (int cl = 0; cl < 8; cl++) dj[cl] = g_dinv[j0 + tx * 8 + cl];

#pragma unroll
    for (int r = 0; r < 8; r++) {
        int gi = i0 + ty * 8 + r;
        const float* arow = A + (size_t)gi * N + j0 + tx * 8;
        float* prow = g_P + (size_t)gi * N + j0 + tx * 8;
#pragma unroll
        for (int cl = 0; cl < 8; cl++) {
            int gj = j0 + tx * 8 + cl;
            float p = di[r] * dj[cl] * (t0 * arow[cl] + t1 * acc[r][cl]);
            if (gi == gj) p += 1.0f;
            prow[cl] = p;
        }
    }
}

// ---------------------------------------------------------------------------
// Kernel 3: row sums of P -> e = rsqrt(rowsum)
// ---------------------------------------------------------------------------
__global__ __launch_bounds__(256) void k_rowsum_P() {
    int row = blockIdx.x;
    const float4* p4 = (const float4*)(g_P + (size_t)row * N);
    float s = 0.f;
    for (int i = threadIdx.x; i < N / 4; i += 256) {
        float4 v = p4[i];
        s += v.x + v.y + v.z + v.w;
    }
    __shared__ float red[256];
    red[threadIdx.x] = s;
    __syncthreads();
    for (int o = 128; o > 0; o >>= 1) {
        if (threadIdx.x < o) red[threadIdx.x] += red[threadIdx.x + o];
        __syncthreads();
    }
    if (threadIdx.x == 0) g_e[row] = rsqrtf(red[0]);
}

// ---------------------------------------------------------------------------
// Kernel 4: per-row top-k of e_i*e_j*P_ij (rank via e_j*P_ij, e_i>0 constant),
//           then y = sum_sel w * x[idx], out = y @ W^T + b. One block per row.
// Tie-break matches stable double-argsort: lowest index wins on equal value.
// ---------------------------------------------------------------------------
__global__ __launch_bounds__(256) void k_topk_out(const float* __restrict__ x,
                                                  const float* __restrict__ W,
                                                  const float* __restrict__ b,
                                                  const int* __restrict__ kp,
                                                  float* __restrict__ out) {
    int row = blockIdx.x;
    int tid = threadIdx.x;
    __shared__ float v[N];            // 16 KB row cache (e_j * P[row][j])
    __shared__ float rv[256];
    __shared__ int   ri[256];
    __shared__ int   sel_i[16];
    __shared__ float sel_v[16];
    __shared__ float y[DIN];

    int k = kp ? *kp : 4;
    if (k < 1) k = 1;
    if (k > 16) k = 16;

    const float* prow = g_P + (size_t)row * N;
    for (int j = tid; j < N; j += 256) v[j] = g_e[j] * prow[j];
    __syncthreads();

    for (int s = 0; s < k; s++) {
        float bv = NEG_HUGE;
        int bi = N;  // thread-local strided scan, strict > keeps lowest j
        for (int j = tid; j < N; j += 256) {
            float val = v[j];
            if (val > bv) { bv = val; bi = j; }
        }
        rv[tid] = bv;
        ri[tid] = bi;
        __syncthreads();
        for (int o = 128; o > 0; o >>= 1) {
            if (tid < o) {
                float ov = rv[tid + o];
                int oi = ri[tid + o];
                if (ov > rv[tid] || (ov == rv[tid] && oi < ri[tid])) {
                    rv[tid] = ov;
                    ri[tid] = oi;
                }
            }
            __syncthreads();
        }
        if (tid == 0) {
            sel_i[s] = ri[0];
            sel_v[s] = rv[0];
            v[ri[0]] = NEG_HUGE;  // exclude from next pass
        }
        __syncthreads();
    }

    float ei = g_e[row];
    if (tid < DIN) {
        float acc = 0.f;
        for (int s = 0; s < k; s++)
            acc += (ei * sel_v[s]) * x[(size_t)sel_i[s] * DIN + tid];
        y[tid] = acc;
    }
    __syncthreads();
    if (tid < DOUT) {
        float acc = b[tid];
        const float* wr = W + tid * DIN;
#pragma unroll
        for (int f = 0; f < DIN; f++) acc += y[f] * wr[f];
        out[(size_t)row * DOUT + tid] = acc;
    }
}

// ---------------------------------------------------------------------------
extern "C" void kernel_launch(void* const* d_in, const int* in_sizes, int n_in,
                              void* d_out, int out_size) {
    const float* x     = (const float*)d_in[0];
    const float* A     = (const float*)d_in[1];
    const float* theta = (const float*)d_in[2];
    const float* W     = (const float*)d_in[3];
    const float* b     = (const float*)d_in[4];
    const int*   kp    = (n_in > 5) ? (const int*)d_in[5] : nullptr;
    float* out = (float*)d_out;

    k_rowsum_A<<<N, 256>>>(A, theta);
    dim3 g(N / BT, N / BT);
    k_gemm_poly<<<g, 256>>>(A);
    k_rowsum_P<<<N, 256>>>();
    k_topk_out<<<N, 256>>>(x, W, b, kp, out);
}

// round 3
// speedup vs baseline: 3.6713x; 3.6713x over previous
#include <cuda_runtime.h>
#include <cstdint>
#include <math.h>

#define N 4096
#define DIN 64
#define DOUT 64
#define NEG_HUGE (-3.402823466e38f)

// ---- scratch (device globals; no runtime allocation) ----
__device__ __align__(16) float g_P[(size_t)N * N];     // 64 MB: final P
__device__ __align__(16) float g_Atc[(size_t)N * N];   // 64 MB: tf32(A^T * c)
__device__ __align__(16) float g_Bt[(size_t)N * N];    // 64 MB: tf32(A)
__device__ __align__(16) float g_dinv[N];
__device__ __align__(16) float g_c[N];
__device__ __align__(16) float g_e[N];
__device__ float g_t[2];

// ===========================================================================
// helpers
// ===========================================================================
__device__ __forceinline__ uint32_t smem_u32(const void* p) {
    uint32_t a;
    asm("{ .reg .u64 t; cvta.to.shared.u64 t, %1; cvt.u32.u64 %0, t; }"
        : "=r"(a) : "l"(p));
    return a;
}
__device__ __forceinline__ float f2tf32(float x) {
    float y;
    asm("cvt.rna.tf32.f32 %0, %1;" : "=f"(y) : "f"(x));
    return y;
}
#define CP_ASYNC16(smem, gptr) \
    asm volatile("cp.async.cg.shared.global [%0], [%1], 16;" \
                 :: "r"(smem), "l"(gptr) : "memory")
#define CP_COMMIT() asm volatile("cp.async.commit_group;" ::: "memory")
#define CP_WAIT(n)  asm volatile("cp.async.wait_group %0;" :: "n"(n) : "memory")

__device__ __forceinline__ void mma_tf32(float* d, const uint32_t* a,
                                         const uint32_t* b) {
    asm volatile(
        "mma.sync.aligned.m16n8k8.row.col.f32.tf32.tf32.f32 "
        "{%0,%1,%2,%3}, {%4,%5,%6,%7}, {%8,%9}, {%0,%1,%2,%3};"
        : "+f"(d[0]), "+f"(d[1]), "+f"(d[2]), "+f"(d[3])
        : "r"(a[0]), "r"(a[1]), "r"(a[2]), "r"(a[3]), "r"(b[0]), "r"(b[1]));
}

// ===========================================================================
// Kernel 1: row sums of A -> dinv, c ; sigmoid(theta)
// ===========================================================================
__global__ __launch_bounds__(256) void k_rowsum_A(const float* __restrict__ A,
                                                  const float* __restrict__ theta) {
    int row = blockIdx.x;
    const float4* a4 = (const float4*)(A + (size_t)row * N);
    float s = 0.f;
    for (int i = threadIdx.x; i < N / 4; i += 256) {
        float4 v = a4[i];
        s += v.x + v.y + v.z + v.w;
    }
    __shared__ float red[256];
    red[threadIdx.x] = s;
    __syncthreads();
    for (int o = 128; o > 0; o >>= 1) {
        if (threadIdx.x < o) red[threadIdx.x] += red[threadIdx.x + o];
        __syncthreads();
    }
    if (threadIdx.x == 0) {
        float d = red[0];
        g_dinv[row] = rsqrtf(d);
        g_c[row] = 1.0f / d;
        if (row == 0) {
            g_t[0] = 1.0f / (1.0f + expf(-theta[0]));
            g_t[1] = 1.0f / (1.0f + expf(-theta[1]));
        }
    }
}

// ===========================================================================
// Kernel 2: prep — g_Bt = tf32(A), g_Atc[k][m] = tf32(A[m][k]*c[k])
// 32x32 tiles, block (32,8)
// ===========================================================================
__global__ __launch_bounds__(256) void k_prep(const float* __restrict__ A) {
    __shared__ float t[32][33];
    int tx = threadIdx.x, ty = threadIdx.y;
    int x0 = blockIdx.x * 32, y0 = blockIdx.y * 32;
    float cc = g_c[x0 + tx];
#pragma unroll
    for (int r = 0; r < 4; r++) {
        int row = y0 + ty + r * 8;
        float v = A[(size_t)row * N + x0 + tx];
        g_Bt[(size_t)row * N + x0 + tx] = f2tf32(v);
        t[ty + r * 8][tx] = f2tf32(v * cc);
    }
    __syncthreads();
#pragma unroll
    for (int r = 0; r < 4; r++) {
        int orow = x0 + ty + r * 8;
        g_Atc[(size_t)orow * N + y0 + tx] = t[tx][ty + r * 8];
    }
}

// ===========================================================================
// Kernel 3: tf32 mma.sync GEMM.  M = Atc^T(as staged) @ Bt -> per CTA 128x128.
// Epilogue: g_P = t1*dinv_i*dinv_j*M + I   (t0*A added in finalize)
// ===========================================================================
#define BK 32
#define NCH (N / BK)            // 128
#define PITCH 136               // floats per smem row (conflict-free banking)
#define TILE_F (BK * PITCH)     // 4352 floats = 17408 B per operand tile
#define STAGE_F (2 * TILE_F)    // 8704 floats per stage (A + B)
#define SMEM_BYTES (2 * STAGE_F * 4)  // 69632

__device__ __forceinline__ void stage_chunk(uint32_t sbase, int buf, int ch,
                                            int i0, int j0, int tid) {
    int k0 = ch * BK;
    uint32_t sa = sbase + buf * (STAGE_F * 4);
    uint32_t sb = sa + TILE_F * 4;
#pragma unroll
    for (int t = 0; t < 4; t++) {
        int id = tid + t * 256;
        int k = id >> 5, seg = id & 31;
        CP_ASYNC16(sa + k * (PITCH * 4) + seg * 16,
                   g_Atc + (size_t)(k0 + k) * N + i0 + seg * 4);
        CP_ASYNC16(sb + k * (PITCH * 4) + seg * 16,
                   g_Bt + (size_t)(k0 + k) * N + j0 + seg * 4);
    }
}

__global__ __launch_bounds__(256, 2) void k_gemm_mma() {
    extern __shared__ float sm[];
    uint32_t sbase = smem_u32(sm);
    int tid = threadIdx.x;
    int wid = tid >> 5, lane = tid & 31;
    int g = lane >> 2, tig = lane & 3;
    int wm0 = (wid & 3) * 32, wn0 = (wid >> 2) * 64;
    int i0 = blockIdx.y * 128, j0 = blockIdx.x * 128;

    float acc[2][8][4];
#pragma unroll
    for (int mt = 0; mt < 2; mt++)
#pragma unroll
        for (int j = 0; j < 8; j++)
#pragma unroll
            for (int c = 0; c < 4; c++) acc[mt][j][c] = 0.f;

    stage_chunk(sbase, 0, 0, i0, j0, tid);
    CP_COMMIT();
    stage_chunk(sbase, 1, 1, i0, j0, tid);
    CP_COMMIT();

    int abase = tig * PITCH + wm0 + g;
    int bbase = tig * PITCH + wn0 + g;

    for (int ch = 0; ch < NCH; ch++) {
        if (ch < NCH - 1) CP_WAIT(1);
        else              CP_WAIT(0);
        __syncthreads();

        const float* As = sm + (ch & 1) * STAGE_F;
        const float* Bs = As + TILE_F;
#pragma unroll
        for (int s = 0; s < 4; s++) {
            int ka = s * (8 * PITCH);
            uint32_t a[2][4];
#pragma unroll
            for (int mt = 0; mt < 2; mt++) {
                int off = ka + abase + 16 * mt;
                a[mt][0] = __float_as_uint(As[off]);
                a[mt][1] = __float_as_uint(As[off + 8]);
                a[mt][2] = __float_as_uint(As[off + 4 * PITCH]);
                a[mt][3] = __float_as_uint(As[off + 4 * PITCH + 8]);
            }
#pragma unroll
            for (int j = 0; j < 8; j++) {
                uint32_t b[2];
                int off = ka + bbase + 8 * j;
                b[0] = __float_as_uint(Bs[off]);
                b[1] = __float_as_uint(Bs[off + 4 * PITCH]);
                mma_tf32(acc[0][j], a[0], b);
                mma_tf32(acc[1][j], a[1], b);
            }
        }
        __syncthreads();
        if (ch + 2 < NCH) {
            stage_chunk(sbase, ch & 1, ch + 2, i0, j0, tid);
            CP_COMMIT();
        }
    }

    // ---- epilogue: scale, diag, transpose through smem, coalesced store ----
    float t1 = g_t[1];
    float* scr = sm;   // 128 x 132 floats = 67584 B (fits in 69632)
#pragma unroll
    for (int mt = 0; mt < 2; mt++) {
        int m0 = wm0 + 16 * mt + g;
        int gi0 = i0 + m0, gi1 = gi0 + 8;
        float di0 = t1 * g_dinv[gi0];
        float di1 = t1 * g_dinv[gi1];
#pragma unroll
        for (int j = 0; j < 8; j++) {
            int n = wn0 + 8 * j + 2 * tig;
            int gj = j0 + n;
            float dj0 = g_dinv[gj], dj1 = g_dinv[gj + 1];
            float p00 = acc[mt][j][0] * di0 * dj0;
            float p01 = acc[mt][j][1] * di0 * dj1;
            float p10 = acc[mt][j][2] * di1 * dj0;
            float p11 = acc[mt][j][3] * di1 * dj1;
            if (gi0 == gj) p00 += 1.0f;
            if (gi0 == gj + 1) p01 += 1.0f;
            if (gi1 == gj) p10 += 1.0f;
            if (gi1 == gj + 1) p11 += 1.0f;
            *(float2*)(scr + m0 * 132 + n) = make_float2(p00, p01);
            *(float2*)(scr + (m0 + 8) * 132 + n) = make_float2(p10, p11);
        }
    }
    __syncthreads();
#pragma unroll
    for (int t = 0; t < 16; t++) {
        int id = tid + t * 256;
        int row = id >> 5, cg = id & 31;
        float4 v = *(float4*)(scr + row * 132 + cg * 4);
        *(float4*)(g_P + (size_t)(i0 + row) * N + j0 + cg * 4) = v;
    }
}

// ===========================================================================
// Kernel 4: finalize P += t0*dinv_i*dinv_j*A (in place), row-sum -> e
// ===========================================================================
__global__ __launch_bounds__(256) void k_finalize_rowsum(const float* __restrict__ A) {
    int row = blockIdx.x;
    float di = g_dinv[row] * g_t[0];
    float4* p4 = (float4*)(g_P + (size_t)row * N);
    const float4* a4 = (const float4*)(A + (size_t)row * N);
    const float4* d4 = (const float4*)g_dinv;
    float s = 0.f;
    for (int i = threadIdx.x; i < N / 4; i += 256) {
        float4 p = p4[i];
        float4 a = a4[i];
        float4 dv = d4[i];
        p.x += di * dv.x * a.x;
        p.y += di * dv.y * a.y;
        p.z += di * dv.z * a.z;
        p.w += di * dv.w * a.w;
        p4[i] = p;
        s += p.x + p.y + p.z + p.w;
    }
    __shared__ float red[256];
    red[threadIdx.x] = s;
    __syncthreads();
    for (int o = 128; o > 0; o >>= 1) {
        if (threadIdx.x < o) red[threadIdx.x] += red[threadIdx.x + o];
        __syncthreads();
    }
    if (threadIdx.x == 0) g_e[row] = rsqrtf(red[0]);
}

// ===========================================================================
// Kernel 5: per-row top-k + gather + linear
// ===========================================================================
__global__ __launch_bounds__(256) void k_topk_out(const float* __restrict__ x,
                                                  const float* __restrict__ W,
                                                  const float* __restrict__ b,
                                                  const int* __restrict__ kp,
                                                  float* __restrict__ out) {
    int row = blockIdx.x;
    int tid = threadIdx.x;
    __shared__ float v[N];
    __shared__ float rv[256];
    __shared__ int ri[256];
    __shared__ int sel_i[16];
    __shared__ float sel_v[16];
    __shared__ float y[DIN];

    int k = kp ? *kp : 4;
    if (k < 1) k = 1;
    if (k > 16) k = 16;

    const float* prow = g_P + (size_t)row * N;
    for (int j = tid; j < N; j += 256) v[j] = g_e[j] * prow[j];
    __syncthreads();

    for (int s = 0; s < k; s++) {
        float bv = NEG_HUGE;
        int bi = N;
        for (int j = tid; j < N; j += 256) {
            float val = v[j];
            if (val > bv) { bv = val; bi = j; }
        }
        rv[tid] = bv;
        ri[tid] = bi;
        __syncthreads();
        for (int o = 128; o > 0; o >>= 1) {
            if (tid < o) {
                float ov = rv[tid + o];
                int oi = ri[tid + o];
                if (ov > rv[tid] || (ov == rv[tid] && oi < ri[tid])) {
                    rv[tid] = ov;
                    ri[tid] = oi;
                }
            }
            __syncthreads();
        }
        if (tid == 0) {
            sel_i[s] = ri[0];
            sel_v[s] = rv[0];
            v[ri[0]] = NEG_HUGE;
        }
        __syncthreads();
    }

    float ei = g_e[row];
    if (tid < DIN) {
        float acc = 0.f;
        for (int s = 0; s < k; s++)
            acc += (ei * sel_v[s]) * x[(size_t)sel_i[s] * DIN + tid];
        y[tid] = acc;
    }
    __syncthreads();
    if (tid < DOUT) {
        float acc = b[tid];
        const float* wr = W + tid * DIN;
#pragma unroll
        for (int f = 0; f < DIN; f++) acc += y[f] * wr[f];
        out[(size_t)row * DOUT + tid] = acc;
    }
}

// ===========================================================================
extern "C" void kernel_launch(void* const* d_in, const int* in_sizes, int n_in,
                              void* d_out, int out_size) {
    const float* x = (const float*)d_in[0];
    const float* A = (const float*)d_in[1];
    const float* theta = (const float*)d_in[2];
    const float* W = (const float*)d_in[3];
    const float* b = (const float*)d_in[4];
    const int* kp = (n_in > 5) ? (const int*)d_in[5] : nullptr;
    float* out = (float*)d_out;

    static bool attr_set = false;
    if (!attr_set) {
        cudaFuncSetAttribute(k_gemm_mma, cudaFuncAttributeMaxDynamicSharedMemorySize,
                             SMEM_BYTES);
        attr_set = true;
    }

    k_rowsum_A<<<N, 256>>>(A, theta);
    dim3 pb(32, 8);
    dim3 pg(N / 32, N / 32);
    k_prep<<<pg, pb>>>(A);
    dim3 gg(N / 128, N / 128);
    k_gemm_mma<<<gg, 256, SMEM_BYTES>>>();
    k_finalize_rowsum<<<N, 256>>>(A);
    k_topk_out<<<N, 256>>>(x, W, b, kp, out);
}